// round 2
// baseline (speedup 1.0000x reference)
#include <cuda_runtime.h>
#include <math.h>

// Problem constants
#define CDIM    64
#define NE      2048
#define HW      4096
#define NPIX    65536            // 16 * 4096
#define NELEM   4194304          // NPIX * CDIM

// Output layout: z_q [NELEM], loss, perplexity, indices [NPIX]
#define OFF_LOSS  NELEM
#define OFF_PERP  (NELEM + 1)
#define OFF_IDX   (NELEM + 2)

// Argmax tiling: tile = 128 pixels x 512 codes  ->  2048 blocks (~7 waves @ occ 2)
#define BP      128
#define QCODES  512
#define NQ      4                // code tiles per pixel tile
#define CHUNK   64               // codes per smem chunk
#define NCH     8                // chunks per tile (QCODES/CHUNK)
#define THREADS 256
#define GRID_ARG ((NPIX / BP) * NQ)   // 2048

#define ZDUP_FLOATS (CDIM * 2 * BP)   // 16384 (pixel-duplicated z tile)
#define EBUF_FLOATS (CHUNK * CDIM)    // 4096  ([k][code] codebook chunk)
#define SMEM_BYTES ((ZDUP_FLOATS + 2 * EBUF_FLOATS) * 4)   // 96 KB

#define OUTBLOCKS 4096

__device__ unsigned long long g_key[NPIX];
__device__ int   g_counts[NE];
__device__ float g_partials[OUTBLOCKS];

// ---------------------------------------------------------------------------
// Kernel 0: zero keys + counts (fresh state per graph replay)
// ---------------------------------------------------------------------------
__global__ void vq_zero() {
    int t = blockIdx.x * 256 + threadIdx.x;
    g_key[t] = 0ull;                     // grid 256 x 256 covers NPIX exactly
    if (blockIdx.x == 0) {
#pragma unroll
        for (int i = 0; i < NE / 256; ++i)
            g_counts[i * 256 + threadIdx.x] = 0;
    }
}

// ---------------------------------------------------------------------------
// Kernel 1: fused GEMM-argmax over a 128px x 512code tile.
// zdup[k][2p] holds pixel-duplicated z (pairs ready for fma.f32x2).
// e tile [k][64 codes], 16B groups XOR-swizzled by (k>>2) -> conflict-free
// transpose-fill AND conflict-free mainloop reads.
// Thread: 4 pixels x 8 codes (codes 4tx..4tx+3 and 32+4tx..+3) = 16 FFMA2/k.
// Partial winners merged globally via atomicMax on monotone (value,idx) key.
// ---------------------------------------------------------------------------
__global__ void __launch_bounds__(THREADS, 2)
vq_argmax(const float* __restrict__ z, const float* __restrict__ cb) {
    extern __shared__ float smem[];
    float* zdup = smem;                        // [64][256]
    float* ebuf = smem + ZDUP_FLOATS;          // 2 x [64][64]

    const int tid = threadIdx.x;
    const int tx  = tid & 7;                   // code group
    const int ty  = tid >> 3;                  // pixel group (4 pixels)

    const int tile    = blockIdx.x;
    const int ptile   = tile >> 2;
    const int q       = tile & 3;
    const int pixBase = ptile * BP;
    const int b       = pixBase >> 12;
    const int hwBase  = pixBase & 4095;
    const int codeBase = q * QCODES;
    const float* zimg = z + (size_t)b * CDIM * HW + hwBase;

    // ---- fill zdup: read z[c][p] float4, write {x,x,y,y},{z,z,w,w} ----
#pragma unroll
    for (int it = 0; it < 8; ++it) {           // 2048 float4 items
        int item = it * THREADS + tid;
        int c = item >> 5, p4 = item & 31;
        float4 v = ((const float4*)(zimg + (size_t)c * HW))[p4];
        float* d = zdup + c * 256 + p4 * 8;
        ((float4*)d)[0] = make_float4(v.x, v.x, v.y, v.y);
        ((float4*)d)[1] = make_float4(v.z, v.z, v.w, v.w);
    }

    // ---- prefetch chunk 0 ----
    float4 pre[4];
    {
        const float4* cbt = (const float4*)(cb + (size_t)codeBase * CDIM);
#pragma unroll
        for (int it = 0; it < 4; ++it)
            pre[it] = cbt[it * THREADS + tid];
    }
    __syncthreads();

    // ---- store chunk 0 (transpose + swizzle) ----
#pragma unroll
    for (int it = 0; it < 4; ++it) {
        int item = it * THREADS + tid;
        int n = item >> 4, kq = item & 15;
        int pg = (n >> 2) ^ kq;
        float* d = ebuf + kq * 256 + pg * 4 + (n & 3);
        d[0] = pre[it].x; d[64] = pre[it].y; d[128] = pre[it].z; d[192] = pre[it].w;
    }
    __syncthreads();

    float mx[4];
    int   mi[4];
#pragma unroll
    for (int m = 0; m < 4; ++m) { mx[m] = -3.402823e38f; mi[m] = 0; }

    for (int ch = 0; ch < NCH; ++ch) {
        const float* es = ebuf + (ch & 1) * EBUF_FLOATS;

        if (ch + 1 < NCH) {
            const float4* cbt =
                (const float4*)(cb + (size_t)(codeBase + (ch + 1) * CHUNK) * CDIM);
#pragma unroll
            for (int it = 0; it < 4; ++it)
                pre[it] = cbt[it * THREADS + tid];
        }

        unsigned long long acc[4][4];
#pragma unroll
        for (int m = 0; m < 4; ++m)
#pragma unroll
            for (int j = 0; j < 4; ++j) acc[m][j] = 0ull;

        const float* zb0 = zdup + (ty << 3);

#pragma unroll 4
        for (int kq = 0; kq < 16; ++kq) {
            const float* er = es + kq * 256;
            const float* zr = zb0 + kq * 1024;
            const int oA = ((tx ^ kq) << 2);
            const int oB = oA ^ 32;
#pragma unroll
            for (int j = 0; j < 4; ++j) {
                const ulonglong2 za = *(const ulonglong2*)(zr + j * 256);
                const ulonglong2 zc = *(const ulonglong2*)(zr + j * 256 + 4);
                const ulonglong2 ea = *(const ulonglong2*)(er + j * 64 + oA);
                const ulonglong2 eb = *(const ulonglong2*)(er + j * 64 + oB);
                unsigned long long zp4[4] = { za.x, za.y, zc.x, zc.y };
#pragma unroll
                for (int m = 0; m < 4; ++m) {
                    asm("fma.rn.f32x2 %0, %1, %2, %0;" : "+l"(acc[m][0]) : "l"(ea.x), "l"(zp4[m]));
                    asm("fma.rn.f32x2 %0, %1, %2, %0;" : "+l"(acc[m][1]) : "l"(ea.y), "l"(zp4[m]));
                    asm("fma.rn.f32x2 %0, %1, %2, %0;" : "+l"(acc[m][2]) : "l"(eb.x), "l"(zp4[m]));
                    asm("fma.rn.f32x2 %0, %1, %2, %0;" : "+l"(acc[m][3]) : "l"(eb.y), "l"(zp4[m]));
                }
            }
        }

        // fold chunk winners (ascending code order within thread -> strict >)
        const int cA = codeBase + ch * CHUNK + (tx << 2);
#pragma unroll
        for (int m = 0; m < 4; ++m) {
#pragma unroll
            for (int j = 0; j < 4; ++j) {
                const int c0 = (j < 2) ? (cA + j * 2) : (cA + 32 + (j - 2) * 2);
                unsigned long long t = acc[m][j];
                float v0 = __uint_as_float((unsigned)t);
                float v1 = __uint_as_float((unsigned)(t >> 32));
                if (v0 > mx[m]) { mx[m] = v0; mi[m] = c0; }
                if (v1 > mx[m]) { mx[m] = v1; mi[m] = c0 + 1; }
            }
        }

        __syncthreads();
        if (ch + 1 < NCH) {
            float* ebN = ebuf + ((ch + 1) & 1) * EBUF_FLOATS;
#pragma unroll
            for (int it = 0; it < 4; ++it) {
                int item = it * THREADS + tid;
                int n = item >> 4, kq = item & 15;
                int pg = (n >> 2) ^ kq;
                float* d = ebN + kq * 256 + pg * 4 + (n & 3);
                d[0] = pre[it].x; d[64] = pre[it].y; d[128] = pre[it].z; d[192] = pre[it].w;
            }
            __syncthreads();
        }
    }

    // ---- reduce across the 8 code-group lanes ----
#pragma unroll
    for (int off = 4; off; off >>= 1) {
#pragma unroll
        for (int m = 0; m < 4; ++m) {
            float om = __shfl_xor_sync(0xFFFFFFFFu, mx[m], off);
            int   oi = __shfl_xor_sync(0xFFFFFFFFu, mi[m], off);
            if (om > mx[m] || (om == mx[m] && oi < mi[m])) { mx[m] = om; mi[m] = oi; }
        }
    }

    if (tx == 0) {
        const int p0 = pixBase + ty * 4;
#pragma unroll
        for (int m = 0; m < 4; ++m) {
            unsigned u = __float_as_uint(mx[m]);
            unsigned menc = (u & 0x80000000u) ? ~u : (u | 0x80000000u);
            unsigned long long key =
                ((unsigned long long)menc << 11) | (unsigned long long)(2047 - mi[m]);
            atomicMax(&g_key[p0 + m], key);
        }
    }
}

// ---------------------------------------------------------------------------
// Kernel 2: decode winners, z_q gather + straight-through output, MSE
// partials, indices output, histogram counts.
// ---------------------------------------------------------------------------
__global__ void __launch_bounds__(256)
vq_out(const float* __restrict__ z, const float* __restrict__ cb,
       float* __restrict__ out, int out_size) {
    const int t = blockIdx.x * 256 + threadIdx.x;   // float4 index
    const int e = t * 4;
    const int c  = (e >> 12) & 63;
    const int b  = e >> 18;
    const int hw = e & 4095;
    const int p  = (b << 12) + hw;

    const float4 zv = *(const float4*)(z + e);
    const unsigned long long k0 = g_key[p];
    const unsigned long long k1 = g_key[p + 1];
    const unsigned long long k2 = g_key[p + 2];
    const unsigned long long k3 = g_key[p + 3];
    const int i0 = 2047 - (int)(k0 & 2047ull);
    const int i1 = 2047 - (int)(k1 & 2047ull);
    const int i2 = 2047 - (int)(k2 & 2047ull);
    const int i3 = 2047 - (int)(k3 & 2047ull);

    const float q0 = cb[i0 * CDIM + c];
    const float q1 = cb[i1 * CDIM + c];
    const float q2 = cb[i2 * CDIM + c];
    const float q3 = cb[i3 * CDIM + c];

    float4 ov;
    ov.x = zv.x + (q0 - zv.x);
    ov.y = zv.y + (q1 - zv.y);
    ov.z = zv.z + (q2 - zv.z);
    ov.w = zv.w + (q3 - zv.w);
    *(float4*)(out + e) = ov;

    if (c == 0) {
        const int o = OFF_IDX + p;
        if (o + 3 < out_size) {
            out[o]     = (float)i0;
            out[o + 1] = (float)i1;
            out[o + 2] = (float)i2;
            out[o + 3] = (float)i3;
        }
        atomicAdd(&g_counts[i0], 1);
        atomicAdd(&g_counts[i1], 1);
        atomicAdd(&g_counts[i2], 1);
        atomicAdd(&g_counts[i3], 1);
    }

    const float d0 = q0 - zv.x, d1 = q1 - zv.y, d2 = q2 - zv.z, d3 = q3 - zv.w;
    float s = d0 * d0 + d1 * d1 + d2 * d2 + d3 * d3;

    __shared__ float red[256];
    red[threadIdx.x] = s;
    __syncthreads();
#pragma unroll
    for (int off = 128; off; off >>= 1) {
        if (threadIdx.x < off) red[threadIdx.x] += red[threadIdx.x + off];
        __syncthreads();
    }
    if (threadIdx.x == 0) g_partials[blockIdx.x] = red[0];
}

// ---------------------------------------------------------------------------
// Kernel 3: deterministic finalize — loss and perplexity (1024 threads).
// ---------------------------------------------------------------------------
__global__ void vq_fin(float* __restrict__ out, int out_size) {
    __shared__ float red[1024];
    const int t = threadIdx.x;

    float s = 0.0f;
#pragma unroll
    for (int i = 0; i < OUTBLOCKS / 1024; ++i) s += g_partials[i * 1024 + t];
    red[t] = s;
    __syncthreads();
#pragma unroll
    for (int off = 512; off; off >>= 1) {
        if (t < off) red[t] += red[t + off];
        __syncthreads();
    }
    if (t == 0 && OFF_LOSS < out_size)
        out[OFF_LOSS] = 1.25f * red[0] * (1.0f / (float)NELEM);
    __syncthreads();

    float h = 0.0f;
#pragma unroll
    for (int i = 0; i < NE / 1024; ++i) {
        float em = (float)g_counts[i * 1024 + t] * (1.0f / (float)NPIX);
        h += em * logf(em + 1e-10f);
    }
    red[t] = h;
    __syncthreads();
#pragma unroll
    for (int off = 512; off; off >>= 1) {
        if (t < off) red[t] += red[t + off];
        __syncthreads();
    }
    if (t == 0 && OFF_PERP < out_size)
        out[OFF_PERP] = expf(-red[0]);
}

// ---------------------------------------------------------------------------
extern "C" void kernel_launch(void* const* d_in, const int* in_sizes, int n_in,
                              void* d_out, int out_size) {
    const float* z  = (const float*)d_in[0];
    const float* cb = (const float*)d_in[1];
    float* out = (float*)d_out;

    cudaFuncSetAttribute(vq_argmax, cudaFuncAttributeMaxDynamicSharedMemorySize,
                         SMEM_BYTES);

    vq_zero<<<256, 256>>>();
    vq_argmax<<<GRID_ARG, THREADS, SMEM_BYTES>>>(z, cb);
    vq_out<<<OUTBLOCKS, 256>>>(z, cb, out, out_size);
    vq_fin<<<1, 1024>>>(out, out_size);
}